// round 7
// baseline (speedup 1.0000x reference)
#include <cuda_runtime.h>

#define N_NODES 100000
#define N_EDGES 3200000
#define N_FEAT  512
#define N_HID   16
#define N_CLS   7

#define SCAN_BLK   1024
#define SCAN_GRID  98            // 98*1024 = 100352 >= N_NODES
#define SCAN_TOT   (SCAN_GRID * SCAN_BLK)

#define GEMMB      148           // gemm blocks inside fused kernels
#define EDGEB      3125          // 3125 * 256 threads * 4 edges = 3.2M

// Scratch (device globals; no allocation allowed)
__device__ __align__(128) float g_h   [N_NODES * N_HID];  // x @ W1
__device__ __align__(128) float g_h2  [N_NODES * 8];      // relu(agg1+b1) @ W2, padded
__device__ __align__(128) int   g_deg [SCAN_TOT];         // per-dst degree
__device__ __align__(128) int   g_off [SCAN_TOT];         // CSR offsets (exclusive scan)
__device__ __align__(128) int   g_pos [N_EDGES];          // within-segment position
__device__ __align__(128) int   g_srcs[N_EDGES];          // CSR: src ids grouped by dst
__device__ __align__(128) volatile unsigned long long g_scan_pkt[SCAN_GRID]; // (flag<<32)|sum

typedef unsigned long long u64;

__device__ __forceinline__ u64 pack2(float a, float b) {
    u64 r; asm("mov.b64 %0, {%1,%2};" : "=l"(r) : "f"(a), "f"(b)); return r;
}
__device__ __forceinline__ void unpack2(u64 v, float& a, float& b) {
    asm("mov.b64 {%0,%1}, %2;" : "=f"(a), "=f"(b) : "l"(v));
}
__device__ __forceinline__ void ffma2(u64& d, u64 a, u64 b) {
    asm("fma.rn.f32x2 %0, %1, %2, %0;" : "+l"(d) : "l"(a), "l"(b));
}
__device__ __forceinline__ void fadd2(u64& d, u64 a) {
    asm("add.rn.f32x2 %0, %0, %1;" : "+l"(d) : "l"(a));
}

// ---------------------------------------------------------------- init
__global__ void init_kernel() {
    int stride = gridDim.x * blockDim.x;
    int i0 = blockIdx.x * blockDim.x + threadIdx.x;
    for (int j = i0; j < SCAN_TOT; j += stride) g_deg[j] = 0;
    for (int j = i0; j < SCAN_GRID; j += stride) g_scan_pkt[j] = 0ull;
}

// ---------------------------------------------------------------- GEMM1 body (device fn)
// h = x @ W1 for row pairs p in [p0, p1), strided by nblk from gblk.
__device__ void gemm_part(const float* __restrict__ x, const float* __restrict__ W1,
                          int gblk, int nblk, int p0, int p1) {
    __shared__ float4 xs[256];   // 2 rows * 512 floats, XOR-swizzled
    const int tid = threadIdx.x;
    const int w = tid >> 5, l = tid & 31;
    const int q = w & 3, s = w >> 2;

    u64 wr0[16], wr1[16];
#pragma unroll
    for (int j = 0; j < 16; j++) {
        float4 wv = *reinterpret_cast<const float4*>(W1 + (l * 16 + j) * 16 + q * 4);
        wr0[j] = pack2(wv.x, wv.y);
        wr1[j] = pack2(wv.z, wv.w);
    }

    float4* h4 = reinterpret_cast<float4*>(g_h);
    const int swz_t = tid ^ ((tid >> 3) & 7);
    const int g0 = s * 128 + l * 4;

    for (int p = p0 + gblk; p < p1; p += nblk) {
        float4 v = reinterpret_cast<const float4*>(x)[(size_t)p * 256 + tid];
        __syncthreads();
        xs[swz_t] = v;
        __syncthreads();

        u64 a0 = 0ull, a1 = 0ull;
#pragma unroll
        for (int i = 0; i < 4; i++) {
            int g = g0 + i;
            float4 xv = xs[g ^ ((g >> 3) & 7)];
            u64 xx;
            xx = pack2(xv.x, xv.x); ffma2(a0, xx, wr0[4*i+0]); ffma2(a1, xx, wr1[4*i+0]);
            xx = pack2(xv.y, xv.y); ffma2(a0, xx, wr0[4*i+1]); ffma2(a1, xx, wr1[4*i+1]);
            xx = pack2(xv.z, xv.z); ffma2(a0, xx, wr0[4*i+2]); ffma2(a1, xx, wr1[4*i+2]);
            xx = pack2(xv.w, xv.w); ffma2(a0, xx, wr0[4*i+3]); ffma2(a1, xx, wr1[4*i+3]);
        }
#pragma unroll
        for (int off = 16; off; off >>= 1) {
            u64 t0 = __shfl_down_sync(0xffffffffu, a0, off);
            u64 t1 = __shfl_down_sync(0xffffffffu, a1, off);
            fadd2(a0, t0); fadd2(a1, t1);
        }
        if (l == 0) {
            float4 o;
            unpack2(a0, o.x, o.y);
            unpack2(a1, o.z, o.w);
            h4[(2 * p + s) * 4 + q] = o;
        }
    }
}

// ---------------------------------------------------------------- fused: hist || gemm half 1
__global__ void __launch_bounds__(256, 2)
histgemmA_kernel(const int* __restrict__ ei,
                 const float* __restrict__ x, const float* __restrict__ W1) {
    if (blockIdx.x < GEMMB) {
        gemm_part(x, W1, blockIdx.x, GEMMB, 0, 25000);
        return;
    }
    int e0 = ((blockIdx.x - GEMMB) * 256 + threadIdx.x) * 4;
    if (e0 >= N_EDGES) return;
    int4 d4 = *reinterpret_cast<const int4*>(ei + N_EDGES + e0);
    int4 p4;
    p4.x = atomicAdd(&g_deg[d4.x], 1);
    p4.y = atomicAdd(&g_deg[d4.y], 1);
    p4.z = atomicAdd(&g_deg[d4.z], 1);
    p4.w = atomicAdd(&g_deg[d4.w], 1);
    *reinterpret_cast<int4*>(g_pos + e0) = p4;
}

// ---------------------------------------------------------------- single-pass scan (decoupled lookback)
// 98 blocks, all resident in wave 1 -> lookback cannot deadlock.
__global__ void __launch_bounds__(SCAN_BLK, 1)
scan_kernel() {
    __shared__ int sd[SCAN_BLK];
    __shared__ int sh_prefix;
    const int t = threadIdx.x, b = blockIdx.x;
    const int g = b * SCAN_BLK + t;
    const int val = g_deg[g];
    sd[t] = val;
    __syncthreads();
    for (int d = 1; d < SCAN_BLK; d <<= 1) {
        int tmp = (t >= d) ? sd[t - d] : 0;
        __syncthreads();
        if (t >= d) sd[t] += tmp;
        __syncthreads();
    }
    const int incl  = sd[t];
    const int total = sd[SCAN_BLK - 1];

    if (t == 0) {
        if (b == 0) { sh_prefix = 0; g_scan_pkt[0] = (2ull << 32) | (unsigned)total; }
        else        { g_scan_pkt[b] = (1ull << 32) | (unsigned)total; }
    }
    __syncthreads();

    if (b > 0 && t < 32) {     // warp 0 lookback, 32-wide windows
        const int lane = t;
        int running = 0;
        int p = b - 1;
        for (;;) {
            int idx = p - lane;
            u64 pkt = 0ull;
            if (idx >= 0) {
                do { pkt = g_scan_pkt[idx]; } while ((unsigned)(pkt >> 32) == 0u);
            }
            unsigned flag = (unsigned)(pkt >> 32);
            unsigned mi = __ballot_sync(0xffffffffu, (idx >= 0) && (flag == 2u));
            int l2 = mi ? (__ffs(mi) - 1) : 32;
            int contrib = ((idx >= 0) && (lane <= l2)) ? (int)(unsigned)pkt : 0;
#pragma unroll
            for (int d = 16; d; d >>= 1) contrib += __shfl_xor_sync(0xffffffffu, contrib, d);
            running += contrib;
            if (mi) break;
            p -= 32;
        }
        if (lane == 0) {
            sh_prefix = running;
            g_scan_pkt[b] = (2ull << 32) | (unsigned)(running + total);
        }
    }
    __syncthreads();
    g_off[g] = sh_prefix + incl - val;
}

// ---------------------------------------------------------------- fused: fill || gemm half 2
__global__ void __launch_bounds__(256, 2)
fillgemmB_kernel(const int* __restrict__ ei,
                 const float* __restrict__ x, const float* __restrict__ W1) {
    if (blockIdx.x < GEMMB) {
        gemm_part(x, W1, blockIdx.x, GEMMB, 25000, 50000);
        return;
    }
    int e0 = ((blockIdx.x - GEMMB) * 256 + threadIdx.x) * 4;
    if (e0 >= N_EDGES) return;
    int4 s4 = *reinterpret_cast<const int4*>(ei + e0);
    int4 d4 = *reinterpret_cast<const int4*>(ei + N_EDGES + e0);
    int4 p4 = *reinterpret_cast<const int4*>(g_pos + e0);
    g_srcs[g_off[d4.x] + p4.x] = s4.x;
    g_srcs[g_off[d4.y] + p4.y] = s4.y;
    g_srcs[g_off[d4.z] + p4.z] = s4.z;
    g_srcs[g_off[d4.w] + p4.w] = s4.w;
}

// ---------------------------------------------------------------- gather1 + fused relu/W2
// Warp per node. Lane = slot*16 + f: feature in lane (coalesced row reads), 2 edge slots.
__global__ void __launch_bounds__(256, 8)
gather1_kernel(const float* __restrict__ W2, const float* __restrict__ b1) {
    const int lane = threadIdx.x & 31;
    const int wid  = threadIdx.x >> 5;
    const int f    = lane & 15;
    const int slot = lane >> 4;
    const int warp_global = blockIdx.x * 8 + wid;
    const int n_warps = gridDim.x * 8;

    float w2r[7];
#pragma unroll
    for (int cc = 0; cc < 7; cc++) w2r[cc] = __ldg(W2 + f * 7 + cc);
    const float b1f = __ldg(b1 + f);

    for (int n = warp_global; n < N_NODES; n += n_warps) {
        const int start = g_off[n];
        const int end   = start + g_deg[n];

        float a0 = 0.f, a1 = 0.f, a2 = 0.f, a3 = 0.f;
        int i = start + slot;
        for (; i + 6 < end; i += 8) {
            int s0 = g_srcs[i];
            int s1 = g_srcs[i + 2];
            int s2 = g_srcs[i + 4];
            int s3 = g_srcs[i + 6];
            a0 += g_h[s0 * 16 + f];
            a1 += g_h[s1 * 16 + f];
            a2 += g_h[s2 * 16 + f];
            a3 += g_h[s3 * 16 + f];
        }
        for (; i < end; i += 2) a0 += g_h[g_srcs[i] * 16 + f];
        float acc = (a0 + a1) + (a2 + a3);
        acc += __shfl_xor_sync(0xffffffffu, acc, 16);

        float r = fmaxf(acc + b1f, 0.f);
        float po[7];
#pragma unroll
        for (int cc = 0; cc < 7; cc++) po[cc] = r * w2r[cc];
#pragma unroll
        for (int d = 8; d; d >>= 1) {
#pragma unroll
            for (int cc = 0; cc < 7; cc++)
                po[cc] += __shfl_xor_sync(0xffffffffu, po[cc], d);
        }
        if (lane == 0) {
            float4* op = reinterpret_cast<float4*>(g_h2) + n * 2;
            op[0] = make_float4(po[0], po[1], po[2], po[3]);
            op[1] = make_float4(po[4], po[5], po[6], 0.f);
        }
    }
}

// ---------------------------------------------------------------- gather2 + fused log_softmax
__global__ void __launch_bounds__(256, 8)
gather2_kernel(const float* __restrict__ b2, float* __restrict__ out) {
    const int lane = threadIdx.x & 31;
    const int wid  = threadIdx.x >> 5;
    const int f    = lane & 7;
    const int slot = lane >> 3;        // 0..3
    const int warp_global = blockIdx.x * 8 + wid;
    const int n_warps = gridDim.x * 8;

    const float b2f = (f < 7) ? __ldg(b2 + f) : 0.f;

    for (int n = warp_global; n < N_NODES; n += n_warps) {
        const int start = g_off[n];
        const int end   = start + g_deg[n];

        float a0 = 0.f, a1 = 0.f, a2 = 0.f, a3 = 0.f;
        int i = start + slot;
        for (; i + 12 < end; i += 16) {
            int s0 = g_srcs[i];
            int s1 = g_srcs[i + 4];
            int s2 = g_srcs[i + 8];
            int s3 = g_srcs[i + 12];
            a0 += g_h2[s0 * 8 + f];
            a1 += g_h2[s1 * 8 + f];
            a2 += g_h2[s2 * 8 + f];
            a3 += g_h2[s3 * 8 + f];
        }
        for (; i < end; i += 4) a0 += g_h2[g_srcs[i] * 8 + f];
        float acc = (a0 + a1) + (a2 + a3);
        acc += __shfl_xor_sync(0xffffffffu, acc, 16);
        acc += __shfl_xor_sync(0xffffffffu, acc, 8);

        float v = acc + b2f;
        float m = (f < 7) ? v : -3.0e38f;
#pragma unroll
        for (int d = 4; d; d >>= 1) m = fmaxf(m, __shfl_xor_sync(0xffffffffu, m, d));
        float ex = (f < 7) ? expf(v - m) : 0.f;
        float ssum = ex;
#pragma unroll
        for (int d = 4; d; d >>= 1) ssum += __shfl_xor_sync(0xffffffffu, ssum, d);
        float lse = m + logf(ssum);
        if (slot == 0 && f < 7) out[(size_t)n * 7 + f] = v - lse;
    }
}

// ----------------------------------------------------------------
// Inputs identified by element count (pairwise distinct):
//   x: 51,200,000  edge_index: 6,400,000  W1: 8,192  W2: 112  b1: 16  b2: 7
extern "C" void kernel_launch(void* const* d_in, const int* in_sizes, int n_in,
                              void* d_out, int out_size) {
    const float* x  = nullptr;
    const int*   ei = nullptr;
    const float* W1 = nullptr;
    const float* b1 = nullptr;
    const float* W2 = nullptr;
    const float* b2 = nullptr;

    for (int i = 0; i < n_in; i++) {
        switch (in_sizes[i]) {
            case N_NODES * N_FEAT: x  = (const float*)d_in[i]; break;
            case 2 * N_EDGES:      ei = (const int*)d_in[i];   break;
            case N_FEAT * N_HID:   W1 = (const float*)d_in[i]; break;
            case N_HID:            b1 = (const float*)d_in[i]; break;
            case N_HID * N_CLS:    W2 = (const float*)d_in[i]; break;
            case N_CLS:            b2 = (const float*)d_in[i]; break;
            default: break;
        }
    }
    float* out = (float*)d_out;

    init_kernel<<<148, 512>>>();
    histgemmA_kernel<<<GEMMB + EDGEB, 256>>>(ei, x, W1);
    scan_kernel<<<SCAN_GRID, SCAN_BLK>>>();
    fillgemmB_kernel<<<GEMMB + EDGEB, 256>>>(ei, x, W1);
    gather1_kernel<<<1184, 256>>>(W2, b1);
    gather2_kernel<<<1184, 256>>>(b2, out);
}

// round 8
// speedup vs baseline: 1.0464x; 1.0464x over previous
#include <cuda_runtime.h>

#define N_NODES 100000
#define N_EDGES 3200000
#define N_FEAT  512
#define N_HID   16
#define N_CLS   7

#define SCAN_BLK   1024
#define SCAN_GRID  98            // 98*1024 = 100352 >= N_NODES
#define SCAN_TOT   (SCAN_GRID * SCAN_BLK)
#define EDGEB      3125          // 3125 * 256 threads * 4 edges = 3.2M

// Scratch (device globals; no allocation allowed).
// NOTE zero-recycling invariants (device globals are zero-initialized at load):
//  - g_deg is zeroed by scan_kernel after consumption -> hist of the NEXT call
//    always starts from zeros (first call: static zero-init).
//  - g_scan_pkt is zeroed at the start of hist_kernel (block 0), which is
//    serialized before scan_kernel in the same call.
__device__ __align__(128) float g_h   [N_NODES * N_HID];  // x @ W1
__device__ __align__(128) float g_h2  [N_NODES * 8];      // relu(agg1+b1) @ W2, padded
__device__ __align__(128) int   g_deg [SCAN_TOT];         // per-dst degree
__device__ __align__(128) int   g_off [SCAN_TOT];         // CSR offsets (exclusive scan)
__device__ __align__(128) int   g_pos [N_EDGES];          // within-segment position
__device__ __align__(128) int   g_srcs[N_EDGES];          // CSR: src ids grouped by dst
__device__ __align__(128) volatile unsigned long long g_scan_pkt[SCAN_GRID]; // (flag<<32)|sum

typedef unsigned long long u64;

__device__ __forceinline__ u64 pack2(float a, float b) {
    u64 r; asm("mov.b64 %0, {%1,%2};" : "=l"(r) : "f"(a), "f"(b)); return r;
}
__device__ __forceinline__ void unpack2(u64 v, float& a, float& b) {
    asm("mov.b64 {%0,%1}, %2;" : "=f"(a), "=f"(b) : "l"(v));
}
__device__ __forceinline__ void ffma2(u64& d, u64 a, u64 b) {
    asm("fma.rn.f32x2 %0, %1, %2, %0;" : "+l"(d) : "l"(a), "l"(b));
}
__device__ __forceinline__ void fadd2(u64& d, u64 a) {
    asm("add.rn.f32x2 %0, %0, %1;" : "+l"(d) : "l"(a));
}

// ---------------------------------------------------------------- degree histogram (+position)
__global__ void __launch_bounds__(256, 8)
hist_kernel(const int* __restrict__ ei) {
    if (blockIdx.x == 0 && threadIdx.x < SCAN_GRID)
        g_scan_pkt[threadIdx.x] = 0ull;          // reset lookback state for this call
    int e0 = (blockIdx.x * 256 + threadIdx.x) * 4;
    if (e0 >= N_EDGES) return;
    int4 d4 = *reinterpret_cast<const int4*>(ei + N_EDGES + e0);
    int4 p4;
    p4.x = atomicAdd(&g_deg[d4.x], 1);
    p4.y = atomicAdd(&g_deg[d4.y], 1);
    p4.z = atomicAdd(&g_deg[d4.z], 1);
    p4.w = atomicAdd(&g_deg[d4.w], 1);
    *reinterpret_cast<int4*>(g_pos + e0) = p4;
}

// ---------------------------------------------------------------- single-pass scan (decoupled lookback)
// 98 blocks, all resident in wave 1 -> lookback cannot deadlock.
// Also re-zeroes g_deg for the next call.
__global__ void __launch_bounds__(SCAN_BLK, 1)
scan_kernel() {
    __shared__ int sd[SCAN_BLK];
    __shared__ int sh_prefix;
    const int t = threadIdx.x, b = blockIdx.x;
    const int g = b * SCAN_BLK + t;
    const int val = g_deg[g];
    g_deg[g] = 0;                                // recycle for next call
    sd[t] = val;
    __syncthreads();
    for (int d = 1; d < SCAN_BLK; d <<= 1) {
        int tmp = (t >= d) ? sd[t - d] : 0;
        __syncthreads();
        if (t >= d) sd[t] += tmp;
        __syncthreads();
    }
    const int incl  = sd[t];
    const int total = sd[SCAN_BLK - 1];

    if (t == 0) {
        if (b == 0) { sh_prefix = 0; g_scan_pkt[0] = (2ull << 32) | (unsigned)total; }
        else        { g_scan_pkt[b] = (1ull << 32) | (unsigned)total; }
    }
    __syncthreads();

    if (b > 0 && t < 32) {     // warp 0 lookback, 32-wide windows
        const int lane = t;
        int running = 0;
        int p = b - 1;
        for (;;) {
            int idx = p - lane;
            u64 pkt = 0ull;
            if (idx >= 0) {
                do { pkt = g_scan_pkt[idx]; } while ((unsigned)(pkt >> 32) == 0u);
            }
            unsigned flag = (unsigned)(pkt >> 32);
            unsigned mi = __ballot_sync(0xffffffffu, (idx >= 0) && (flag == 2u));
            int l2 = mi ? (__ffs(mi) - 1) : 32;
            int contrib = ((idx >= 0) && (lane <= l2)) ? (int)(unsigned)pkt : 0;
#pragma unroll
            for (int d = 16; d; d >>= 1) contrib += __shfl_xor_sync(0xffffffffu, contrib, d);
            running += contrib;
            if (mi) break;
            p -= 32;
        }
        if (lane == 0) {
            sh_prefix = running;
            g_scan_pkt[b] = (2ull << 32) | (unsigned)(running + total);
        }
    }
    __syncthreads();
    g_off[g] = sh_prefix + incl - val;
}

// ---------------------------------------------------------------- CSR fill (atomic-free)
__global__ void __launch_bounds__(256, 8)
fill_kernel(const int* __restrict__ ei) {
    int e0 = (blockIdx.x * 256 + threadIdx.x) * 4;
    if (e0 >= N_EDGES) return;
    int4 s4 = *reinterpret_cast<const int4*>(ei + e0);
    int4 d4 = *reinterpret_cast<const int4*>(ei + N_EDGES + e0);
    int4 p4 = *reinterpret_cast<const int4*>(g_pos + e0);
    g_srcs[g_off[d4.x] + p4.x] = s4.x;
    g_srcs[g_off[d4.y] + p4.y] = s4.y;
    g_srcs[g_off[d4.z] + p4.z] = s4.z;
    g_srcs[g_off[d4.w] + p4.w] = s4.w;
}

// ---------------------------------------------------------------- GEMM1: h = x @ W1
__global__ void __launch_bounds__(256, 2)
gemm1_kernel(const float* __restrict__ x, const float* __restrict__ W1) {
    __shared__ float4 xs[256];   // 2 rows * 512 floats, XOR-swizzled
    const int tid = threadIdx.x;
    const int w = tid >> 5, l = tid & 31;
    const int q = w & 3, s = w >> 2;

    u64 wr0[16], wr1[16];
#pragma unroll
    for (int j = 0; j < 16; j++) {
        float4 wv = *reinterpret_cast<const float4*>(W1 + (l * 16 + j) * 16 + q * 4);
        wr0[j] = pack2(wv.x, wv.y);
        wr1[j] = pack2(wv.z, wv.w);
    }

    float4* h4 = reinterpret_cast<float4*>(g_h);
    const int swz_t = tid ^ ((tid >> 3) & 7);
    const int g0 = s * 128 + l * 4;

    for (int p = blockIdx.x; p < N_NODES / 2; p += gridDim.x) {
        float4 v = reinterpret_cast<const float4*>(x)[(size_t)p * 256 + tid];
        __syncthreads();
        xs[swz_t] = v;
        __syncthreads();

        u64 a0 = 0ull, a1 = 0ull;
#pragma unroll
        for (int i = 0; i < 4; i++) {
            int g = g0 + i;
            float4 xv = xs[g ^ ((g >> 3) & 7)];
            u64 xx;
            xx = pack2(xv.x, xv.x); ffma2(a0, xx, wr0[4*i+0]); ffma2(a1, xx, wr1[4*i+0]);
            xx = pack2(xv.y, xv.y); ffma2(a0, xx, wr0[4*i+1]); ffma2(a1, xx, wr1[4*i+1]);
            xx = pack2(xv.z, xv.z); ffma2(a0, xx, wr0[4*i+2]); ffma2(a1, xx, wr1[4*i+2]);
            xx = pack2(xv.w, xv.w); ffma2(a0, xx, wr0[4*i+3]); ffma2(a1, xx, wr1[4*i+3]);
        }
#pragma unroll
        for (int off = 16; off; off >>= 1) {
            u64 t0 = __shfl_down_sync(0xffffffffu, a0, off);
            u64 t1 = __shfl_down_sync(0xffffffffu, a1, off);
            fadd2(a0, t0); fadd2(a1, t1);
        }
        if (l == 0) {
            float4 o;
            unpack2(a0, o.x, o.y);
            unpack2(a1, o.z, o.w);
            h4[(2 * p + s) * 4 + q] = o;
        }
    }
}

// ---------------------------------------------------------------- gather1 + fused relu/W2
// Warp per node. Lane = slot*16 + f: feature in lane (coalesced row reads), 2 edge slots.
__global__ void __launch_bounds__(256, 8)
gather1_kernel(const float* __restrict__ W2, const float* __restrict__ b1) {
    const int lane = threadIdx.x & 31;
    const int wid  = threadIdx.x >> 5;
    const int f    = lane & 15;
    const int slot = lane >> 4;
    const int warp_global = blockIdx.x * 8 + wid;
    const int n_warps = gridDim.x * 8;

    float w2r[7];
#pragma unroll
    for (int cc = 0; cc < 7; cc++) w2r[cc] = __ldg(W2 + f * 7 + cc);
    const float b1f = __ldg(b1 + f);

    for (int n = warp_global; n < N_NODES; n += n_warps) {
        const int start = g_off[n];
        const int end   = g_off[n + 1];

        float a0 = 0.f, a1 = 0.f, a2 = 0.f, a3 = 0.f;
        int i = start + slot;
        for (; i + 6 < end; i += 8) {
            int s0 = g_srcs[i];
            int s1 = g_srcs[i + 2];
            int s2 = g_srcs[i + 4];
            int s3 = g_srcs[i + 6];
            a0 += g_h[s0 * 16 + f];
            a1 += g_h[s1 * 16 + f];
            a2 += g_h[s2 * 16 + f];
            a3 += g_h[s3 * 16 + f];
        }
        for (; i < end; i += 2) a0 += g_h[g_srcs[i] * 16 + f];
        float acc = (a0 + a1) + (a2 + a3);
        acc += __shfl_xor_sync(0xffffffffu, acc, 16);

        float r = fmaxf(acc + b1f, 0.f);
        float po[7];
#pragma unroll
        for (int cc = 0; cc < 7; cc++) po[cc] = r * w2r[cc];
#pragma unroll
        for (int d = 8; d; d >>= 1) {
#pragma unroll
            for (int cc = 0; cc < 7; cc++)
                po[cc] += __shfl_xor_sync(0xffffffffu, po[cc], d);
        }
        if (lane == 0) {
            float4* op = reinterpret_cast<float4*>(g_h2) + n * 2;
            op[0] = make_float4(po[0], po[1], po[2], po[3]);
            op[1] = make_float4(po[4], po[5], po[6], 0.f);
        }
    }
}

// ---------------------------------------------------------------- gather2 + fused log_softmax
__global__ void __launch_bounds__(256, 8)
gather2_kernel(const float* __restrict__ b2, float* __restrict__ out) {
    const int lane = threadIdx.x & 31;
    const int wid  = threadIdx.x >> 5;
    const int f    = lane & 7;
    const int slot = lane >> 3;        // 0..3
    const int warp_global = blockIdx.x * 8 + wid;
    const int n_warps = gridDim.x * 8;

    const float b2f = (f < 7) ? __ldg(b2 + f) : 0.f;

    for (int n = warp_global; n < N_NODES; n += n_warps) {
        const int start = g_off[n];
        const int end   = g_off[n + 1];

        float a0 = 0.f, a1 = 0.f, a2 = 0.f, a3 = 0.f;
        int i = start + slot;
        for (; i + 12 < end; i += 16) {
            int s0 = g_srcs[i];
            int s1 = g_srcs[i + 4];
            int s2 = g_srcs[i + 8];
            int s3 = g_srcs[i + 12];
            a0 += g_h2[s0 * 8 + f];
            a1 += g_h2[s1 * 8 + f];
            a2 += g_h2[s2 * 8 + f];
            a3 += g_h2[s3 * 8 + f];
        }
        for (; i < end; i += 4) a0 += g_h2[g_srcs[i] * 8 + f];
        float acc = (a0 + a1) + (a2 + a3);
        acc += __shfl_xor_sync(0xffffffffu, acc, 16);
        acc += __shfl_xor_sync(0xffffffffu, acc, 8);

        float v = acc + b2f;
        float m = (f < 7) ? v : -3.0e38f;
#pragma unroll
        for (int d = 4; d; d >>= 1) m = fmaxf(m, __shfl_xor_sync(0xffffffffu, m, d));
        float ex = (f < 7) ? expf(v - m) : 0.f;
        float ssum = ex;
#pragma unroll
        for (int d = 4; d; d >>= 1) ssum += __shfl_xor_sync(0xffffffffu, ssum, d);
        float lse = m + logf(ssum);
        if (slot == 0 && f < 7) out[(size_t)n * 7 + f] = v - lse;
    }
}

// ----------------------------------------------------------------
// Inputs identified by element count (pairwise distinct):
//   x: 51,200,000  edge_index: 6,400,000  W1: 8,192  W2: 112  b1: 16  b2: 7
extern "C" void kernel_launch(void* const* d_in, const int* in_sizes, int n_in,
                              void* d_out, int out_size) {
    const float* x  = nullptr;
    const int*   ei = nullptr;
    const float* W1 = nullptr;
    const float* b1 = nullptr;
    const float* W2 = nullptr;
    const float* b2 = nullptr;

    for (int i = 0; i < n_in; i++) {
        switch (in_sizes[i]) {
            case N_NODES * N_FEAT: x  = (const float*)d_in[i]; break;
            case 2 * N_EDGES:      ei = (const int*)d_in[i];   break;
            case N_FEAT * N_HID:   W1 = (const float*)d_in[i]; break;
            case N_HID:            b1 = (const float*)d_in[i]; break;
            case N_HID * N_CLS:    W2 = (const float*)d_in[i]; break;
            case N_CLS:            b2 = (const float*)d_in[i]; break;
            default: break;
        }
    }
    float* out = (float*)d_out;

    hist_kernel<<<EDGEB, 256>>>(ei);
    scan_kernel<<<SCAN_GRID, SCAN_BLK>>>();
    fill_kernel<<<EDGEB, 256>>>(ei);
    gemm1_kernel<<<296, 256>>>(x, W1);
    gather1_kernel<<<1184, 256>>>(W2, b1);
    gather2_kernel<<<1184, 256>>>(b2, out);
}

// round 9
// speedup vs baseline: 1.1775x; 1.1253x over previous
#include <cuda_runtime.h>

#define N_NODES 100000
#define N_EDGES 3200000
#define N_FEAT  512
#define N_HID   16
#define N_CLS   7

#define SCAN_BLK   1024
#define SCAN_GRID  98            // 98*1024 = 100352 >= N_NODES
#define SCAN_TOT   (SCAN_GRID * SCAN_BLK)
#define EDGEB      3125          // 3125 * 256 threads * 4 edges = 3.2M
#define GROWS      8             // rows per gemm tile

// Scratch (device globals; no allocation allowed).
// Zero-recycling invariants (device globals zero-initialized at load):
//  - g_deg zeroed by scan_kernel after consumption -> next call's hist starts at 0.
//  - g_scan_pkt zeroed by hist_kernel block 0 (serialized before scan).
__device__ __align__(128) float g_h   [N_NODES * N_HID];  // x @ W1
__device__ __align__(128) float g_h2  [N_NODES * 8];      // relu(agg1+b1) @ W2, padded
__device__ __align__(128) int   g_deg [SCAN_TOT];         // per-dst degree
__device__ __align__(128) int   g_off [SCAN_TOT];         // CSR offsets (exclusive scan)
__device__ __align__(128) int   g_pos [N_EDGES];          // within-segment position
__device__ __align__(128) int   g_srcs[N_EDGES];          // CSR: src ids grouped by dst
__device__ __align__(128) volatile unsigned long long g_scan_pkt[SCAN_GRID]; // (flag<<32)|sum

typedef unsigned long long u64;

__device__ __forceinline__ u64 pack2(float a, float b) {
    u64 r; asm("mov.b64 %0, {%1,%2};" : "=l"(r) : "f"(a), "f"(b)); return r;
}
__device__ __forceinline__ void unpack2(u64 v, float& a, float& b) {
    asm("mov.b64 {%0,%1}, %2;" : "=f"(a), "=f"(b) : "l"(v));
}
__device__ __forceinline__ void ffma2(u64& d, u64 a, u64 b) {
    asm("fma.rn.f32x2 %0, %1, %2, %0;" : "+l"(d) : "l"(a), "l"(b));
}
__device__ __forceinline__ void fadd2(u64& d, u64 a) {
    asm("add.rn.f32x2 %0, %0, %1;" : "+l"(d) : "l"(a));
}

// ---------------------------------------------------------------- degree histogram (+position)
__global__ void __launch_bounds__(256, 8)
hist_kernel(const int* __restrict__ ei) {
    if (blockIdx.x == 0 && threadIdx.x < SCAN_GRID)
        g_scan_pkt[threadIdx.x] = 0ull;          // reset lookback state for this call
    int e0 = (blockIdx.x * 256 + threadIdx.x) * 4;
    if (e0 >= N_EDGES) return;
    int4 d4 = *reinterpret_cast<const int4*>(ei + N_EDGES + e0);
    int4 p4;
    p4.x = atomicAdd(&g_deg[d4.x], 1);
    p4.y = atomicAdd(&g_deg[d4.y], 1);
    p4.z = atomicAdd(&g_deg[d4.z], 1);
    p4.w = atomicAdd(&g_deg[d4.w], 1);
    *reinterpret_cast<int4*>(g_pos + e0) = p4;
}

// ---------------------------------------------------------------- single-pass scan (decoupled lookback)
// 98 blocks, all resident in wave 1 -> lookback cannot deadlock.
// Also re-zeroes g_deg for the next call.
__global__ void __launch_bounds__(SCAN_BLK, 1)
scan_kernel() {
    __shared__ int sd[SCAN_BLK];
    __shared__ int sh_prefix;
    const int t = threadIdx.x, b = blockIdx.x;
    const int g = b * SCAN_BLK + t;
    const int val = g_deg[g];
    g_deg[g] = 0;                                // recycle for next call
    sd[t] = val;
    __syncthreads();
    for (int d = 1; d < SCAN_BLK; d <<= 1) {
        int tmp = (t >= d) ? sd[t - d] : 0;
        __syncthreads();
        if (t >= d) sd[t] += tmp;
        __syncthreads();
    }
    const int incl  = sd[t];
    const int total = sd[SCAN_BLK - 1];

    if (t == 0) {
        if (b == 0) { sh_prefix = 0; g_scan_pkt[0] = (2ull << 32) | (unsigned)total; }
        else        { g_scan_pkt[b] = (1ull << 32) | (unsigned)total; }
    }
    __syncthreads();

    if (b > 0 && t < 32) {     // warp 0 lookback, 32-wide windows
        const int lane = t;
        int running = 0;
        int p = b - 1;
        for (;;) {
            int idx = p - lane;
            u64 pkt = 0ull;
            if (idx >= 0) {
                do { pkt = g_scan_pkt[idx]; } while ((unsigned)(pkt >> 32) == 0u);
            }
            unsigned flag = (unsigned)(pkt >> 32);
            unsigned mi = __ballot_sync(0xffffffffu, (idx >= 0) && (flag == 2u));
            int l2 = mi ? (__ffs(mi) - 1) : 32;
            int contrib = ((idx >= 0) && (lane <= l2)) ? (int)(unsigned)pkt : 0;
#pragma unroll
            for (int d = 16; d; d >>= 1) contrib += __shfl_xor_sync(0xffffffffu, contrib, d);
            running += contrib;
            if (mi) break;
            p -= 32;
        }
        if (lane == 0) {
            sh_prefix = running;
            g_scan_pkt[b] = (2ull << 32) | (unsigned)(running + total);
        }
    }
    __syncthreads();
    g_off[g] = sh_prefix + incl - val;
}

// ---------------------------------------------------------------- CSR fill (atomic-free)
__global__ void __launch_bounds__(256, 8)
fill_kernel(const int* __restrict__ ei) {
    int e0 = (blockIdx.x * 256 + threadIdx.x) * 4;
    if (e0 >= N_EDGES) return;
    int4 s4 = *reinterpret_cast<const int4*>(ei + e0);
    int4 d4 = *reinterpret_cast<const int4*>(ei + N_EDGES + e0);
    int4 p4 = *reinterpret_cast<const int4*>(g_pos + e0);
    g_srcs[g_off[d4.x] + p4.x] = s4.x;
    g_srcs[g_off[d4.y] + p4.y] = s4.y;
    g_srcs[g_off[d4.z] + p4.z] = s4.z;
    g_srcs[g_off[d4.w] + p4.w] = s4.w;
}

// ---------------------------------------------------------------- GEMM1: h = x @ W1
// 8-row tiles staged in smem. Warp w owns cols {2w, 2w+1}; lane l owns
// k in [16l, 16l+16) with W held in 16 packed-f32x2 regs. 8 independent
// accumulator chains (one per row) -> pipelined shuffles. 3 blocks/SM.
__global__ void __launch_bounds__(256, 3)
gemm1_kernel(const float* __restrict__ x, const float* __restrict__ W1) {
    __shared__ float4 xs[GROWS * 128];   // 16KB, XOR-swizzled granules
    const int tid = threadIdx.x;
    const int w = tid >> 5, l = tid & 31;

    u64 wr[16];
#pragma unroll
    for (int j = 0; j < 16; j++) {
        const float* wp = W1 + (l * 16 + j) * 16 + 2 * w;
        wr[j] = pack2(wp[0], wp[1]);
    }

    const float4* x4 = reinterpret_cast<const float4*>(x);
    const int ntiles = N_NODES / GROWS;   // 12500

    for (int tile = blockIdx.x; tile < ntiles; tile += gridDim.x) {
        // stage 8 rows (4 coalesced LDG.128 per thread, MLP=4)
        size_t base = (size_t)tile * (GROWS * 128);
        float4 v0 = x4[base + tid];
        float4 v1 = x4[base + 256 + tid];
        float4 v2 = x4[base + 512 + tid];
        float4 v3 = x4[base + 768 + tid];
        __syncthreads();
        {
            int i0 = tid;       xs[i0 ^ ((i0 >> 3) & 7)] = v0;
            int i1 = tid + 256; xs[i1 ^ ((i1 >> 3) & 7)] = v1;
            int i2 = tid + 512; xs[i2 ^ ((i2 >> 3) & 7)] = v2;
            int i3 = tid + 768; xs[i3 ^ ((i3 >> 3) & 7)] = v3;
        }
        __syncthreads();

        u64 acc[GROWS];
#pragma unroll
        for (int r = 0; r < GROWS; r++) acc[r] = 0ull;
#pragma unroll
        for (int r = 0; r < GROWS; r++) {
#pragma unroll
            for (int j4 = 0; j4 < 4; j4++) {
                int g = r * 128 + l * 4 + j4;
                float4 xv = xs[g ^ ((g >> 3) & 7)];
                u64 xx;
                xx = pack2(xv.x, xv.x); ffma2(acc[r], xx, wr[j4 * 4 + 0]);
                xx = pack2(xv.y, xv.y); ffma2(acc[r], xx, wr[j4 * 4 + 1]);
                xx = pack2(xv.z, xv.z); ffma2(acc[r], xx, wr[j4 * 4 + 2]);
                xx = pack2(xv.w, xv.w); ffma2(acc[r], xx, wr[j4 * 4 + 3]);
            }
        }
        // 8 independent butterfly reductions (pipelined)
#pragma unroll
        for (int r = 0; r < GROWS; r++) {
#pragma unroll
            for (int d = 16; d; d >>= 1) {
                u64 t = __shfl_xor_sync(0xffffffffu, acc[r], d);
                fadd2(acc[r], t);
            }
        }
        if (l == 0) {
#pragma unroll
            for (int r = 0; r < GROWS; r++) {
                float a, b; unpack2(acc[r], a, b);
                *reinterpret_cast<float2*>(g_h + (tile * GROWS + r) * 16 + 2 * w)
                    = make_float2(a, b);
            }
        }
    }
}

// ---------------------------------------------------------------- gather1 + fused relu/W2
// Warp per node. Lane = slot*16 + f: feature in lane (coalesced row reads), 2 edge slots.
__global__ void __launch_bounds__(256, 8)
gather1_kernel(const float* __restrict__ W2, const float* __restrict__ b1) {
    const int lane = threadIdx.x & 31;
    const int wid  = threadIdx.x >> 5;
    const int f    = lane & 15;
    const int slot = lane >> 4;
    const int warp_global = blockIdx.x * 8 + wid;
    const int n_warps = gridDim.x * 8;

    float w2r[7];
#pragma unroll
    for (int cc = 0; cc < 7; cc++) w2r[cc] = __ldg(W2 + f * 7 + cc);
    const float b1f = __ldg(b1 + f);

    for (int n = warp_global; n < N_NODES; n += n_warps) {
        const int start = g_off[n];
        const int end   = g_off[n + 1];

        float a0 = 0.f, a1 = 0.f, a2 = 0.f, a3 = 0.f;
        int i = start + slot;
        for (; i + 6 < end; i += 8) {
            int s0 = g_srcs[i];
            int s1 = g_srcs[i + 2];
            int s2 = g_srcs[i + 4];
            int s3 = g_srcs[i + 6];
            a0 += g_h[s0 * 16 + f];
            a1 += g_h[s1 * 16 + f];
            a2 += g_h[s2 * 16 + f];
            a3 += g_h[s3 * 16 + f];
        }
        for (; i < end; i += 2) a0 += g_h[g_srcs[i] * 16 + f];
        float acc = (a0 + a1) + (a2 + a3);
        acc += __shfl_xor_sync(0xffffffffu, acc, 16);

        float r = fmaxf(acc + b1f, 0.f);
        float po[7];
#pragma unroll
        for (int cc = 0; cc < 7; cc++) po[cc] = r * w2r[cc];
#pragma unroll
        for (int d = 8; d; d >>= 1) {
#pragma unroll
            for (int cc = 0; cc < 7; cc++)
                po[cc] += __shfl_xor_sync(0xffffffffu, po[cc], d);
        }
        if (lane == 0) {
            float4* op = reinterpret_cast<float4*>(g_h2) + n * 2;
            op[0] = make_float4(po[0], po[1], po[2], po[3]);
            op[1] = make_float4(po[4], po[5], po[6], 0.f);
        }
    }
}

// ---------------------------------------------------------------- gather2 + fused log_softmax
__global__ void __launch_bounds__(256, 8)
gather2_kernel(const float* __restrict__ b2, float* __restrict__ out) {
    const int lane = threadIdx.x & 31;
    const int wid  = threadIdx.x >> 5;
    const int f    = lane & 7;
    const int slot = lane >> 3;        // 0..3
    const int warp_global = blockIdx.x * 8 + wid;
    const int n_warps = gridDim.x * 8;

    const float b2f = (f < 7) ? __ldg(b2 + f) : 0.f;

    for (int n = warp_global; n < N_NODES; n += n_warps) {
        const int start = g_off[n];
        const int end   = g_off[n + 1];

        float a0 = 0.f, a1 = 0.f, a2 = 0.f, a3 = 0.f;
        int i = start + slot;
        for (; i + 12 < end; i += 16) {
            int s0 = g_srcs[i];
            int s1 = g_srcs[i + 4];
            int s2 = g_srcs[i + 8];
            int s3 = g_srcs[i + 12];
            a0 += g_h2[s0 * 8 + f];
            a1 += g_h2[s1 * 8 + f];
            a2 += g_h2[s2 * 8 + f];
            a3 += g_h2[s3 * 8 + f];
        }
        for (; i < end; i += 4) a0 += g_h2[g_srcs[i] * 8 + f];
        float acc = (a0 + a1) + (a2 + a3);
        acc += __shfl_xor_sync(0xffffffffu, acc, 16);
        acc += __shfl_xor_sync(0xffffffffu, acc, 8);

        float v = acc + b2f;
        float m = (f < 7) ? v : -3.0e38f;
#pragma unroll
        for (int d = 4; d; d >>= 1) m = fmaxf(m, __shfl_xor_sync(0xffffffffu, m, d));
        float ex = (f < 7) ? expf(v - m) : 0.f;
        float ssum = ex;
#pragma unroll
        for (int d = 4; d; d >>= 1) ssum += __shfl_xor_sync(0xffffffffu, ssum, d);
        float lse = m + logf(ssum);
        if (slot == 0 && f < 7) out[(size_t)n * 7 + f] = v - lse;
    }
}

// ----------------------------------------------------------------
// Inputs identified by element count (pairwise distinct):
//   x: 51,200,000  edge_index: 6,400,000  W1: 8,192  W2: 112  b1: 16  b2: 7
extern "C" void kernel_launch(void* const* d_in, const int* in_sizes, int n_in,
                              void* d_out, int out_size) {
    const float* x  = nullptr;
    const int*   ei = nullptr;
    const float* W1 = nullptr;
    const float* b1 = nullptr;
    const float* W2 = nullptr;
    const float* b2 = nullptr;

    for (int i = 0; i < n_in; i++) {
        switch (in_sizes[i]) {
            case N_NODES * N_FEAT: x  = (const float*)d_in[i]; break;
            case 2 * N_EDGES:      ei = (const int*)d_in[i];   break;
            case N_FEAT * N_HID:   W1 = (const float*)d_in[i]; break;
            case N_HID:            b1 = (const float*)d_in[i]; break;
            case N_HID * N_CLS:    W2 = (const float*)d_in[i]; break;
            case N_CLS:            b2 = (const float*)d_in[i]; break;
            default: break;
        }
    }
    float* out = (float*)d_out;

    hist_kernel<<<EDGEB, 256>>>(ei);
    scan_kernel<<<SCAN_GRID, SCAN_BLK>>>();
    fill_kernel<<<EDGEB, 256>>>(ei);
    gemm1_kernel<<<444, 256>>>(x, W1);
    gather1_kernel<<<1184, 256>>>(W2, b1);
    gather2_kernel<<<1184, 256>>>(b2, out);
}

// round 10
// speedup vs baseline: 1.3124x; 1.1145x over previous
#include <cuda_runtime.h>

#define N_NODES 100000
#define N_EDGES 3200000
#define N_FEAT  512
#define N_HID   16
#define N_CLS   7

#define SCAN_BLK   1024
#define SCAN_GRID  98            // 98*1024 = 100352 >= N_NODES
#define SCAN_TOT   (SCAN_GRID * SCAN_BLK)
#define EDGEB      3125          // 3125 * 256 threads * 4 edges = 3.2M
#define GROWS      8             // rows per gemm tile

// Scratch (device globals; no allocation allowed).
// Zero-recycling invariants (device globals zero-initialized at load):
//  - g_deg zeroed by scan_kernel after consumption -> next call's hist starts at 0.
//  - g_scan_pkt zeroed by hist_kernel block 0 (serialized before scan).
__device__ __align__(128) float g_h   [N_NODES * N_HID];  // x @ W1
__device__ __align__(128) float g_h2  [N_NODES * 8];      // relu(agg1+b1) @ W2, padded
__device__ __align__(128) int   g_deg [SCAN_TOT];         // per-dst degree
__device__ __align__(128) int   g_off [SCAN_TOT];         // CSR offsets (exclusive scan)
__device__ __align__(128) int   g_pos [N_EDGES];          // within-segment position
__device__ __align__(128) int   g_srcs[N_EDGES];          // CSR: src ids grouped by dst
__device__ __align__(128) volatile unsigned long long g_scan_pkt[SCAN_GRID]; // (flag<<32)|sum

typedef unsigned long long u64;

__device__ __forceinline__ u64 pack2(float a, float b) {
    u64 r; asm("mov.b64 %0, {%1,%2};" : "=l"(r) : "f"(a), "f"(b)); return r;
}
__device__ __forceinline__ void unpack2(u64 v, float& a, float& b) {
    asm("mov.b64 {%0,%1}, %2;" : "=f"(a), "=f"(b) : "l"(v));
}
__device__ __forceinline__ void ffma2(u64& d, u64 a, u64 b) {
    asm("fma.rn.f32x2 %0, %1, %2, %0;" : "+l"(d) : "l"(a), "l"(b));
}
__device__ __forceinline__ void fadd2(u64& d, u64 a) {
    asm("add.rn.f32x2 %0, %0, %1;" : "+l"(d) : "l"(a));
}

// ---------------------------------------------------------------- degree histogram (+position)
__global__ void __launch_bounds__(256, 8)
hist_kernel(const int* __restrict__ ei) {
    if (blockIdx.x == 0 && threadIdx.x < SCAN_GRID)
        g_scan_pkt[threadIdx.x] = 0ull;          // reset lookback state for this call
    int e0 = (blockIdx.x * 256 + threadIdx.x) * 4;
    if (e0 >= N_EDGES) return;
    int4 d4 = *reinterpret_cast<const int4*>(ei + N_EDGES + e0);
    int4 p4;
    p4.x = atomicAdd(&g_deg[d4.x], 1);
    p4.y = atomicAdd(&g_deg[d4.y], 1);
    p4.z = atomicAdd(&g_deg[d4.z], 1);
    p4.w = atomicAdd(&g_deg[d4.w], 1);
    *reinterpret_cast<int4*>(g_pos + e0) = p4;
}

// ---------------------------------------------------------------- single-pass scan (decoupled lookback)
// 98 blocks, all resident in wave 1 -> lookback cannot deadlock.
// Also re-zeroes g_deg for the next call.
__global__ void __launch_bounds__(SCAN_BLK, 1)
scan_kernel() {
    __shared__ int sd[SCAN_BLK];
    __shared__ int sh_prefix;
    const int t = threadIdx.x, b = blockIdx.x;
    const int g = b * SCAN_BLK + t;
    const int val = g_deg[g];
    g_deg[g] = 0;                                // recycle for next call
    sd[t] = val;
    __syncthreads();
    for (int d = 1; d < SCAN_BLK; d <<= 1) {
        int tmp = (t >= d) ? sd[t - d] : 0;
        __syncthreads();
        if (t >= d) sd[t] += tmp;
        __syncthreads();
    }
    const int incl  = sd[t];
    const int total = sd[SCAN_BLK - 1];

    if (t == 0) {
        if (b == 0) { sh_prefix = 0; g_scan_pkt[0] = (2ull << 32) | (unsigned)total; }
        else        { g_scan_pkt[b] = (1ull << 32) | (unsigned)total; }
    }
    __syncthreads();

    if (b > 0 && t < 32) {     // warp 0 lookback, 32-wide windows
        const int lane = t;
        int running = 0;
        int p = b - 1;
        for (;;) {
            int idx = p - lane;
            u64 pkt = 0ull;
            if (idx >= 0) {
                do { pkt = g_scan_pkt[idx]; } while ((unsigned)(pkt >> 32) == 0u);
            }
            unsigned flag = (unsigned)(pkt >> 32);
            unsigned mi = __ballot_sync(0xffffffffu, (idx >= 0) && (flag == 2u));
            int l2 = mi ? (__ffs(mi) - 1) : 32;
            int contrib = ((idx >= 0) && (lane <= l2)) ? (int)(unsigned)pkt : 0;
#pragma unroll
            for (int d = 16; d; d >>= 1) contrib += __shfl_xor_sync(0xffffffffu, contrib, d);
            running += contrib;
            if (mi) break;
            p -= 32;
        }
        if (lane == 0) {
            sh_prefix = running;
            g_scan_pkt[b] = (2ull << 32) | (unsigned)(running + total);
        }
    }
    __syncthreads();
    g_off[g] = sh_prefix + incl - val;
}

// ---------------------------------------------------------------- CSR fill (atomic-free)
__global__ void __launch_bounds__(256, 8)
fill_kernel(const int* __restrict__ ei) {
    int e0 = (blockIdx.x * 256 + threadIdx.x) * 4;
    if (e0 >= N_EDGES) return;
    int4 s4 = *reinterpret_cast<const int4*>(ei + e0);
    int4 d4 = *reinterpret_cast<const int4*>(ei + N_EDGES + e0);
    int4 p4 = *reinterpret_cast<const int4*>(g_pos + e0);
    g_srcs[g_off[d4.x] + p4.x] = s4.x;
    g_srcs[g_off[d4.y] + p4.y] = s4.y;
    g_srcs[g_off[d4.z] + p4.z] = s4.z;
    g_srcs[g_off[d4.w] + p4.w] = s4.w;
}

// ---------------------------------------------------------------- GEMM1: h = x @ W1
// 8-row tiles in smem. Warp w: row-group s = w>>2 (4 rows), col-quad q = w&3
// (4 cols) -> each warp reads only its 4 rows: LDS amplification 4 (was 8).
// Lane l owns k [16l,16l+16) with W in 32 packed-f32x2 regs. Software
// pipeline: next tile's LDGs issued before current tile's FMA phase.
__global__ void __launch_bounds__(256, 2)
gemm1_kernel(const float* __restrict__ x, const float* __restrict__ W1) {
    __shared__ float4 xs[GROWS * 128];   // 16KB, XOR-swizzled granules
    const int tid = threadIdx.x;
    const int w = tid >> 5, l = tid & 31;
    const int q = w & 3, s = w >> 2;

    u64 wr0[16], wr1[16];
#pragma unroll
    for (int j = 0; j < 16; j++) {
        float4 wv = *reinterpret_cast<const float4*>(W1 + (l * 16 + j) * 16 + q * 4);
        wr0[j] = pack2(wv.x, wv.y);
        wr1[j] = pack2(wv.z, wv.w);
    }

    const float4* x4 = reinterpret_cast<const float4*>(x);
    const int ntiles = N_NODES / GROWS;   // 12500

    int tile = blockIdx.x;
    float4 v0, v1, v2, v3;
    if (tile < ntiles) {
        size_t base = (size_t)tile * (GROWS * 128);
        v0 = x4[base + tid];
        v1 = x4[base + 256 + tid];
        v2 = x4[base + 512 + tid];
        v3 = x4[base + 768 + tid];
    }

    while (tile < ntiles) {
        __syncthreads();      // prior tile's readers done
        {
            int i0 = tid;       xs[i0 ^ ((i0 >> 3) & 7)] = v0;
            int i1 = tid + 256; xs[i1 ^ ((i1 >> 3) & 7)] = v1;
            int i2 = tid + 512; xs[i2 ^ ((i2 >> 3) & 7)] = v2;
            int i3 = tid + 768; xs[i3 ^ ((i3 >> 3) & 7)] = v3;
        }
        __syncthreads();

        const int next = tile + gridDim.x;
        if (next < ntiles) {  // prefetch next tile during compute
            size_t base = (size_t)next * (GROWS * 128);
            v0 = x4[base + tid];
            v1 = x4[base + 256 + tid];
            v2 = x4[base + 512 + tid];
            v3 = x4[base + 768 + tid];
        }

        u64 a0[4], a1[4];
#pragma unroll
        for (int r = 0; r < 4; r++) { a0[r] = 0ull; a1[r] = 0ull; }
#pragma unroll
        for (int r = 0; r < 4; r++) {
            const int row = s * 4 + r;
#pragma unroll
            for (int j4 = 0; j4 < 4; j4++) {
                int g = row * 128 + l * 4 + j4;
                float4 xv = xs[g ^ ((g >> 3) & 7)];
                u64 xx;
                xx = pack2(xv.x, xv.x); ffma2(a0[r], xx, wr0[j4*4+0]); ffma2(a1[r], xx, wr1[j4*4+0]);
                xx = pack2(xv.y, xv.y); ffma2(a0[r], xx, wr0[j4*4+1]); ffma2(a1[r], xx, wr1[j4*4+1]);
                xx = pack2(xv.z, xv.z); ffma2(a0[r], xx, wr0[j4*4+2]); ffma2(a1[r], xx, wr1[j4*4+2]);
                xx = pack2(xv.w, xv.w); ffma2(a0[r], xx, wr0[j4*4+3]); ffma2(a1[r], xx, wr1[j4*4+3]);
            }
        }
        // 8 independent butterfly reductions (pipelined)
#pragma unroll
        for (int r = 0; r < 4; r++) {
#pragma unroll
            for (int d = 16; d; d >>= 1) {
                u64 t0 = __shfl_xor_sync(0xffffffffu, a0[r], d);
                u64 t1 = __shfl_xor_sync(0xffffffffu, a1[r], d);
                fadd2(a0[r], t0); fadd2(a1[r], t1);
            }
        }
        if (l == 0) {
#pragma unroll
            for (int r = 0; r < 4; r++) {
                float c0, c1, c2, c3;
                unpack2(a0[r], c0, c1);
                unpack2(a1[r], c2, c3);
                *reinterpret_cast<float4*>(g_h + (tile * GROWS + s * 4 + r) * 16 + q * 4)
                    = make_float4(c0, c1, c2, c3);
            }
        }
        tile = next;
    }
}

// ---------------------------------------------------------------- gather1 + fused relu/W2
// Warp per node. Lane = slot*16 + f: feature in lane (coalesced row reads), 2 edge slots.
__global__ void __launch_bounds__(256, 8)
gather1_kernel(const float* __restrict__ W2, const float* __restrict__ b1) {
    const int lane = threadIdx.x & 31;
    const int wid  = threadIdx.x >> 5;
    const int f    = lane & 15;
    const int slot = lane >> 4;
    const int warp_global = blockIdx.x * 8 + wid;
    const int n_warps = gridDim.x * 8;

    float w2r[7];
#pragma unroll
    for (int cc = 0; cc < 7; cc++) w2r[cc] = __ldg(W2 + f * 7 + cc);
    const float b1f = __ldg(b1 + f);

    for (int n = warp_global; n < N_NODES; n += n_warps) {
        const int start = g_off[n];
        const int end   = g_off[n + 1];

        float a0 = 0.f, a1 = 0.f, a2 = 0.f, a3 = 0.f;
        int i = start + slot;
        for (; i + 6 < end; i += 8) {
            int s0 = g_srcs[i];
            int s1 = g_srcs[i + 2];
            int s2 = g_srcs[i + 4];
            int s3 = g_srcs[i + 6];
            a0 += g_h[s0 * 16 + f];
            a1 += g_h[s1 * 16 + f];
            a2 += g_h[s2 * 16 + f];
            a3 += g_h[s3 * 16 + f];
        }
        for (; i < end; i += 2) a0 += g_h[g_srcs[i] * 16 + f];
        float acc = (a0 + a1) + (a2 + a3);
        acc += __shfl_xor_sync(0xffffffffu, acc, 16);

        float r = fmaxf(acc + b1f, 0.f);
        float po[7];
#pragma unroll
        for (int cc = 0; cc < 7; cc++) po[cc] = r * w2r[cc];
#pragma unroll
        for (int d = 8; d; d >>= 1) {
#pragma unroll
            for (int cc = 0; cc < 7; cc++)
                po[cc] += __shfl_xor_sync(0xffffffffu, po[cc], d);
        }
        if (lane == 0) {
            float4* op = reinterpret_cast<float4*>(g_h2) + n * 2;
            op[0] = make_float4(po[0], po[1], po[2], po[3]);
            op[1] = make_float4(po[4], po[5], po[6], 0.f);
        }
    }
}

// ---------------------------------------------------------------- gather2 + fused log_softmax
__global__ void __launch_bounds__(256, 8)
gather2_kernel(const float* __restrict__ b2, float* __restrict__ out) {
    const int lane = threadIdx.x & 31;
    const int wid  = threadIdx.x >> 5;
    const int f    = lane & 7;
    const int slot = lane >> 3;        // 0..3
    const int warp_global = blockIdx.x * 8 + wid;
    const int n_warps = gridDim.x * 8;

    const float b2f = (f < 7) ? __ldg(b2 + f) : 0.f;

    for (int n = warp_global; n < N_NODES; n += n_warps) {
        const int start = g_off[n];
        const int end   = g_off[n + 1];

        float a0 = 0.f, a1 = 0.f, a2 = 0.f, a3 = 0.f;
        int i = start + slot;
        for (; i + 12 < end; i += 16) {
            int s0 = g_srcs[i];
            int s1 = g_srcs[i + 4];
            int s2 = g_srcs[i + 8];
            int s3 = g_srcs[i + 12];
            a0 += g_h2[s0 * 8 + f];
            a1 += g_h2[s1 * 8 + f];
            a2 += g_h2[s2 * 8 + f];
            a3 += g_h2[s3 * 8 + f];
        }
        for (; i < end; i += 4) a0 += g_h2[g_srcs[i] * 8 + f];
        float acc = (a0 + a1) + (a2 + a3);
        acc += __shfl_xor_sync(0xffffffffu, acc, 16);
        acc += __shfl_xor_sync(0xffffffffu, acc, 8);

        float v = acc + b2f;
        float m = (f < 7) ? v : -3.0e38f;
#pragma unroll
        for (int d = 4; d; d >>= 1) m = fmaxf(m, __shfl_xor_sync(0xffffffffu, m, d));
        float ex = (f < 7) ? expf(v - m) : 0.f;
        float ssum = ex;
#pragma unroll
        for (int d = 4; d; d >>= 1) ssum += __shfl_xor_sync(0xffffffffu, ssum, d);
        float lse = m + logf(ssum);
        if (slot == 0 && f < 7) out[(size_t)n * 7 + f] = v - lse;
    }
}

// ----------------------------------------------------------------
// Inputs identified by element count (pairwise distinct):
//   x: 51,200,000  edge_index: 6,400,000  W1: 8,192  W2: 112  b1: 16  b2: 7
extern "C" void kernel_launch(void* const* d_in, const int* in_sizes, int n_in,
                              void* d_out, int out_size) {
    const float* x  = nullptr;
    const int*   ei = nullptr;
    const float* W1 = nullptr;
    const float* b1 = nullptr;
    const float* W2 = nullptr;
    const float* b2 = nullptr;

    for (int i = 0; i < n_in; i++) {
        switch (in_sizes[i]) {
            case N_NODES * N_FEAT: x  = (const float*)d_in[i]; break;
            case 2 * N_EDGES:      ei = (const int*)d_in[i];   break;
            case N_FEAT * N_HID:   W1 = (const float*)d_in[i]; break;
            case N_HID:            b1 = (const float*)d_in[i]; break;
            case N_HID * N_CLS:    W2 = (const float*)d_in[i]; break;
            case N_CLS:            b2 = (const float*)d_in[i]; break;
            default: break;
        }
    }
    float* out = (float*)d_out;

    hist_kernel<<<EDGEB, 256>>>(ei);
    scan_kernel<<<SCAN_GRID, SCAN_BLK>>>();
    fill_kernel<<<EDGEB, 256>>>(ei);
    gemm1_kernel<<<296, 256>>>(x, W1);
    gather1_kernel<<<1184, 256>>>(W2, b1);
    gather2_kernel<<<1184, 256>>>(b2, out);
}